// round 5
// baseline (speedup 1.0000x reference)
#include <cuda_runtime.h>
#include <math.h>

#define S_LEN 512
#define B_SZ  64
#define HID   512
#define G3    1536
#define EMB_D 256
#define M_ROWS (S_LEN * B_SZ)   // 32768

typedef unsigned long long ull;

// ---------------- packed f32x2 helpers --------------------------------------
__device__ __forceinline__ ull pk2(float lo, float hi) {
    ull r; asm("mov.b64 %0, {%1,%2};" : "=l"(r) : "f"(lo), "f"(hi)); return r;
}
__device__ __forceinline__ ull dup2(float v) { return pk2(v, v); }
__device__ __forceinline__ void ffma2(ull& d, ull a, ull b) {
    asm("fma.rn.f32x2 %0, %1, %2, %0;" : "+l"(d) : "l"(a), "l"(b));
}
__device__ __forceinline__ float2 unpk2(ull v) {
    float2 f; asm("mov.b64 {%0,%1}, %2;" : "=f"(f.x), "=f"(f.y) : "l"(v)); return f;
}

// ---------------- scratch (static device globals; no allocation) ------------
__device__ float g_xemb[(size_t)M_ROWS * EMB_D];   // 32 MB
__device__ float g_xg  [(size_t)M_ROWS * G3];      // 192 MB
__device__ float g_ys  [(size_t)M_ROWS * HID];     // 64 MB
// one flag per producer block, each on its own 128B L2 line
__device__ unsigned int g_flags[4][32][32];

// ---------------- embedding gather ------------------------------------------
__global__ void embed_kernel(const int* __restrict__ x,
                             const float* __restrict__ emb,
                             float* __restrict__ out) {
    int w    = (blockIdx.x << 3) + (threadIdx.x >> 5);  // row m = s*64+b
    int lane = threadIdx.x & 31;
    int s = w >> 6, b = w & 63;
    int tok = x[b * S_LEN + s];
    float4* dst = (float4*)(out + (size_t)w * EMB_D);
    if (tok == 0) {  // PAD_IDX row zeroed
        float4 z = make_float4(0.f, 0.f, 0.f, 0.f);
        dst[lane] = z; dst[lane + 32] = z;
    } else {
        const float4* src = (const float4*)(emb + (size_t)tok * EMB_D);
        dst[lane] = src[lane]; dst[lane + 32] = src[lane + 32];
    }
}

// ---------------- C[M,N] = A[M,K] @ W[N,K]^T + bias[N] ----------------------
__global__ void __launch_bounds__(256, 2) gemm_bias_kernel(
    const float* __restrict__ A, const float* __restrict__ W,
    const float* __restrict__ bias, float* __restrict__ C,
    int M, int N, int K) {
    __shared__ float As[2][16][128];
    __shared__ float Bs[2][16][128];

    const int tid = threadIdx.x;
    const int n0 = blockIdx.x * 128;
    const int m0 = blockIdx.y * 128;
    const int tx = tid & 15, ty = tid >> 4;

    ull acc2[4][8];
#pragma unroll
    for (int p = 0; p < 4; p++)
#pragma unroll
        for (int j = 0; j < 8; j++) acc2[p][j] = 0ULL;

    const int KT = K >> 4;

#pragma unroll
    for (int i = 0; i < 2; i++) {
        int id = tid * 2 + i, row = id >> 2, kq = id & 3;
        float4 va = *(const float4*)(A + (size_t)(m0 + row) * K + kq * 4);
        float4 vb = *(const float4*)(W + (size_t)(n0 + row) * K + kq * 4);
        As[0][kq * 4 + 0][row] = va.x; As[0][kq * 4 + 1][row] = va.y;
        As[0][kq * 4 + 2][row] = va.z; As[0][kq * 4 + 3][row] = va.w;
        Bs[0][kq * 4 + 0][row] = vb.x; Bs[0][kq * 4 + 1][row] = vb.y;
        Bs[0][kq * 4 + 2][row] = vb.z; Bs[0][kq * 4 + 3][row] = vb.w;
    }
    __syncthreads();

    for (int kt = 0; kt < KT; ++kt) {
        const int cur = kt & 1;
        float4 pa[2], pb[2];
        const bool pf = (kt + 1) < KT;
        if (pf) {
#pragma unroll
            for (int i = 0; i < 2; i++) {
                int id = tid * 2 + i, row = id >> 2, kq = id & 3;
                pa[i] = *(const float4*)(A + (size_t)(m0 + row) * K + (kt + 1) * 16 + kq * 4);
                pb[i] = *(const float4*)(W + (size_t)(n0 + row) * K + (kt + 1) * 16 + kq * 4);
            }
        }
#pragma unroll
        for (int kk = 0; kk < 16; kk++) {
            ull ap[4];
            ap[0] = *(const ull*)&As[cur][kk][ty * 4];
            ap[1] = *(const ull*)&As[cur][kk][ty * 4 + 2];
            ap[2] = *(const ull*)&As[cur][kk][64 + ty * 4];
            ap[3] = *(const ull*)&As[cur][kk][64 + ty * 4 + 2];
            float b[8];
            *(float4*)(b)     = *(const float4*)&Bs[cur][kk][tx * 4];
            *(float4*)(b + 4) = *(const float4*)&Bs[cur][kk][64 + tx * 4];
#pragma unroll
            for (int j = 0; j < 8; j++) {
                ull bd = dup2(b[j]);
#pragma unroll
                for (int p = 0; p < 4; p++) ffma2(acc2[p][j], ap[p], bd);
            }
        }
        if (pf) {
            const int nxt = cur ^ 1;
#pragma unroll
            for (int i = 0; i < 2; i++) {
                int id = tid * 2 + i, row = id >> 2, kq = id & 3;
                As[nxt][kq * 4 + 0][row] = pa[i].x; As[nxt][kq * 4 + 1][row] = pa[i].y;
                As[nxt][kq * 4 + 2][row] = pa[i].z; As[nxt][kq * 4 + 3][row] = pa[i].w;
                Bs[nxt][kq * 4 + 0][row] = pb[i].x; Bs[nxt][kq * 4 + 1][row] = pb[i].y;
                Bs[nxt][kq * 4 + 2][row] = pb[i].z; Bs[nxt][kq * 4 + 3][row] = pb[i].w;
            }
        }
        __syncthreads();
    }

    float4 bb0 = *(const float4*)&bias[n0 + tx * 4];
    float4 bb1 = *(const float4*)&bias[n0 + 64 + tx * 4];
#pragma unroll
    for (int p = 0; p < 4; p++) {
        float2 c[8];
#pragma unroll
        for (int j = 0; j < 8; j++) c[j] = unpk2(acc2[p][j]);
#pragma unroll
        for (int half = 0; half < 2; half++) {
            int i = 2 * p + half;
            int m = m0 + ((i < 4) ? (ty * 4 + i) : (64 + ty * 4 + i - 4));
            float e[8];
#pragma unroll
            for (int j = 0; j < 8; j++) e[j] = half ? c[j].y : c[j].x;
            float4 v0 = make_float4(e[0] + bb0.x, e[1] + bb0.y,
                                    e[2] + bb0.z, e[3] + bb0.w);
            float4 v1 = make_float4(e[4] + bb1.x, e[5] + bb1.y,
                                    e[6] + bb1.z, e[7] + bb1.w);
            *(float4*)(C + (size_t)m * N + n0 + tx * 4)      = v0;
            *(float4*)(C + (size_t)m * N + n0 + 64 + tx * 4) = v1;
        }
    }
}

// ---------------- GRU recurrence ---------------------------------------------
// 128 blocks = 4 batch groups (16 rows) x 32 dim groups (16 dims), 512 threads.
// smem: Wsh [512][48] k-major (col = dimLocal*3+gate)  = 96KB
//       hsh [512][16] swizzled by ((k>>1)^(k>>5))&15   = 32KB
//       part[16 kgroups][256 rowdim][4]                = 64KB
#define GRU_SMEM_BYTES ((512 * 48 + 512 * 16 + 16 * 256 * 4) * 4)

__device__ __forceinline__ unsigned ld_acq(const unsigned* p) {
    unsigned v;
    asm volatile("ld.global.acquire.gpu.u32 %0, [%1];" : "=r"(v) : "l"(p) : "memory");
    return v;
}
__device__ __forceinline__ void st_rel(unsigned* p, unsigned v) {
    asm volatile("st.global.release.gpu.u32 [%0], %1;" :: "l"(p), "r"(v) : "memory");
}
__device__ __forceinline__ int hswz(int k) { return ((k >> 1) ^ (k >> 5)) & 15; }

__global__ void __launch_bounds__(512, 1) gru_kernel(
    const float* __restrict__ xg,    // [S][64][1536]
    const float* __restrict__ Whh,   // [1536][512]
    const float* __restrict__ bhh,   // [1536]
    float* __restrict__ ys)          // [S][64][512]
{
    extern __shared__ float sm[];
    float* Wsh  = sm;                  // 512*48
    float* hsh  = Wsh + 512 * 48;      // 512*16
    float* part = hsh + 512 * 16;      // 16*256*4
    __shared__ unsigned sh_base;

    const int tid = threadIdx.x;
    const int bg  = blockIdx.x & 3;
    const int dg  = blockIdx.x >> 2;
    const int rowBase = bg * 16;
    const int dimBase = dg * 16;

    if (tid == 0) sh_base = *(volatile unsigned*)&g_flags[bg][dg][0];

    // load W_hh slice (48 gate rows) into smem, k-major
    for (int idx = tid; idx < 48 * 512; idx += 512) {
        int col = idx >> 9;       // 0..47
        int k   = idx & 511;
        int dl = col / 3, g = col % 3;
        int grow = g * 512 + dimBase + dl;
        Wsh[k * 48 + col] = Whh[(size_t)grow * 512 + k];
    }

    // gating role (tid < 256): one thread per (row, dim)
    const int myrow = (tid >> 4) & 15;
    const int mydl  = tid & 15;
    const int mydim = dimBase + mydl;
    float b_r = 0.f, b_z = 0.f, b_n = 0.f;
    if (tid < 256) {
        b_r = bhh[mydim]; b_z = bhh[512 + mydim]; b_n = bhh[1024 + mydim];
    }

    // compute role: 16 k-groups (32 k each), per warp: 8 rowpairs x 4 dimquads
    const int kg  = tid >> 5;             // 0..15
    const int pos = tid & 31;
    const int rg  = pos >> 2;             // 0..7  -> rows {2rg, 2rg+1}
    const int dgi = pos & 3;              // 0..3  -> dims [4dgi, 4dgi+4)

    __syncthreads();
    const unsigned base = sh_base;

    for (int t = 0; t < S_LEN; ++t) {
        // prefetch xg for gating (consumed after the GEMM)
        float xr = 0.f, xz = 0.f, xn = 0.f;
        if (tid < 256) {
            size_t xbase = ((size_t)t * 64 + rowBase + myrow) * G3 + mydim;
            xr = xg[xbase]; xz = xg[xbase + 512]; xn = xg[xbase + 1024];
        }

        if (t == 0) {
            for (int idx = tid; idx < 512 * 16; idx += 512) hsh[idx] = 0.f;
        } else {
            // wait for the 32 producer blocks of this batch group
            if (tid < 32) {
                const unsigned target = base + (unsigned)t;
                const unsigned* fp = &g_flags[bg][tid][0];
                while ((int)(ld_acq(fp) - target) < 0) { }
            }
            __syncthreads();
            // load h(t-1): 4 LDG.128 per thread, swizzled STS
            const float4* hsrc4 = (const float4*)(ys + ((size_t)(t - 1) * 64 + rowBase) * HID);
            float4 v[4];
#pragma unroll
            for (int i = 0; i < 4; i++) v[i] = __ldcg(hsrc4 + tid + 512 * i);
#pragma unroll
            for (int i = 0; i < 4; i++) {
                int q = tid + 512 * i;
                int r = q >> 7, k4 = (q & 127) << 2;
#pragma unroll
                for (int j = 0; j < 4; j++) {
                    int k = k4 + j;
                    ((float*)hsh)[k * 16 + (r ^ hswz(k))] =
                        (j == 0) ? v[i].x : (j == 1) ? v[i].y : (j == 2) ? v[i].z : v[i].w;
                }
            }
        }
        __syncthreads();

        // hg partials: 2 rows x 4 dims x 3 gates = 12 f32x2 accumulators
        ull acc2[12];
#pragma unroll
        for (int i = 0; i < 12; i++) acc2[i] = 0ULL;
        const int k0 = kg * 32;
        const float* Wp = Wsh + dgi * 12;
        const int rb = rg * 2;
#pragma unroll 4
        for (int k = k0; k < k0 + 32; ++k) {
            const float* wk = Wp + k * 48;
            ull w0 = *(const ull*)(wk);
            ull w1 = *(const ull*)(wk + 2);
            ull w2 = *(const ull*)(wk + 4);
            ull w3 = *(const ull*)(wk + 6);
            ull w4 = *(const ull*)(wk + 8);
            ull w5 = *(const ull*)(wk + 10);
            const int sw = hswz(k);
            const float* hk = hsh + k * 16;
            ull h0 = dup2(hk[rb ^ sw]);
            ull h1 = dup2(hk[(rb + 1) ^ sw]);
            ffma2(acc2[0], h0, w0); ffma2(acc2[1], h0, w1); ffma2(acc2[2], h0, w2);
            ffma2(acc2[3], h0, w3); ffma2(acc2[4], h0, w4); ffma2(acc2[5], h0, w5);
            ffma2(acc2[6], h1, w0); ffma2(acc2[7], h1, w1); ffma2(acc2[8], h1, w2);
            ffma2(acc2[9], h1, w3); ffma2(acc2[10], h1, w4); ffma2(acc2[11], h1, w5);
        }
        // write partials (gate triplets per (row,dim), float4-padded)
#pragma unroll
        for (int i = 0; i < 2; i++) {
            float2 v0 = unpk2(acc2[i * 6 + 0]);
            float2 v1 = unpk2(acc2[i * 6 + 1]);
            float2 v2 = unpk2(acc2[i * 6 + 2]);
            float2 v3 = unpk2(acc2[i * 6 + 3]);
            float2 v4 = unpk2(acc2[i * 6 + 4]);
            float2 v5 = unpk2(acc2[i * 6 + 5]);
            int rd0 = (rb + i) * 16 + dgi * 4;
            float* p = part + (kg * 256 + rd0) * 4;
            *(float4*)(p + 0)  = make_float4(v0.x, v0.y, v1.x, 0.f);
            *(float4*)(p + 4)  = make_float4(v1.y, v2.x, v2.y, 0.f);
            *(float4*)(p + 8)  = make_float4(v3.x, v3.y, v4.x, 0.f);
            *(float4*)(p + 12) = make_float4(v4.y, v5.x, v5.y, 0.f);
        }
        __syncthreads();

        // reduce 16 k-groups + gate, one thread per (row, dim)
        if (tid < 256) {
            float hr = b_r, hz = b_z, hn = b_n;
#pragma unroll
            for (int kk = 0; kk < 16; kk++) {
                float4 p = *(const float4*)(part + (kk * 256 + tid) * 4);
                hr += p.x; hz += p.y; hn += p.z;
            }
            float h_old = hsh[mydim * 16 + (myrow ^ hswz(mydim))];
            float er = __expf(-(xr + hr));
            float rr = __fdividef(1.f, 1.f + er);
            float ez = __expf(-(xz + hz));
            float zz = __fdividef(1.f, 1.f + ez);
            float an = xn + rr * hn;
            float e2 = __expf(2.f * an);
            float nn = 1.f - __fdividef(2.f, e2 + 1.f);   // tanh(an)
            float hnew = (1.f - zz) * nn + zz * h_old;
            ys[((size_t)t * 64 + rowBase + myrow) * HID + mydim] = hnew;
        }

        __syncthreads();   // all STG issued before release (st.release orders them)
        if (tid == 0) st_rel(&g_flags[bg][dg][0], base + (unsigned)t + 1u);
    }
}

// ---------------- final FC + sigmoid ----------------------------------------
__global__ void fc_kernel(const float* __restrict__ ys,
                          const float* __restrict__ Wfc,
                          const float* __restrict__ bfc,
                          float* __restrict__ out) {
    int b = blockIdx.x, tid = threadIdx.x;  // 128 threads
    const float* h = ys + ((size_t)(S_LEN - 1) * 64 + b) * HID;
    float s = 0.f;
    for (int i = tid; i < HID; i += 128) s += h[i] * Wfc[i];
#pragma unroll
    for (int o = 16; o; o >>= 1) s += __shfl_down_sync(0xffffffffu, s, o);
    __shared__ float ps[4];
    if ((tid & 31) == 0) ps[tid >> 5] = s;
    __syncthreads();
    if (tid == 0) {
        float v = ps[0] + ps[1] + ps[2] + ps[3] + bfc[0];
        out[b] = 1.f / (1.f + expf(-v));
    }
}

// ---------------- launch ----------------------------------------------------
extern "C" void kernel_launch(void* const* d_in, const int* in_sizes, int n_in,
                              void* d_out, int out_size) {
    (void)in_sizes; (void)n_in; (void)out_size;
    const int*   x    = (const int*)  d_in[0];
    const float* emb  = (const float*)d_in[1];
    const float* Wih0 = (const float*)d_in[2];
    const float* Whh0 = (const float*)d_in[3];
    const float* bih0 = (const float*)d_in[4];
    const float* bhh0 = (const float*)d_in[5];
    const float* Wih1 = (const float*)d_in[6];
    const float* Whh1 = (const float*)d_in[7];
    const float* bih1 = (const float*)d_in[8];
    const float* bhh1 = (const float*)d_in[9];
    const float* Wfc  = (const float*)d_in[10];
    const float* bfc  = (const float*)d_in[11];
    float* out = (float*)d_out;

    float *xemb, *xgbuf, *ysbuf;
    cudaGetSymbolAddress((void**)&xemb,  g_xemb);
    cudaGetSymbolAddress((void**)&xgbuf, g_xg);
    cudaGetSymbolAddress((void**)&ysbuf, g_ys);

    cudaFuncSetAttribute(gru_kernel, cudaFuncAttributeMaxDynamicSharedMemorySize,
                         GRU_SMEM_BYTES);

    embed_kernel<<<4096, 256>>>(x, emb, xemb);
    gemm_bias_kernel<<<dim3(G3 / 128, M_ROWS / 128), 256>>>(
        xemb, Wih0, bih0, xgbuf, M_ROWS, G3, EMB_D);
    gru_kernel<<<128, 512, GRU_SMEM_BYTES>>>(xgbuf, Whh0, bhh0, ysbuf);
    gemm_bias_kernel<<<dim3(G3 / 128, M_ROWS / 128), 256>>>(
        ysbuf, Wih1, bih1, xgbuf, M_ROWS, G3, HID);
    gru_kernel<<<128, 512, GRU_SMEM_BYTES>>>(xgbuf, Whh1, bhh1, ysbuf);
    fc_kernel<<<64, 128>>>(ysbuf, Wfc, bfc, out);
}

// round 6
// speedup vs baseline: 1.1213x; 1.1213x over previous
#include <cuda_runtime.h>
#include <math.h>

#define S_LEN 512
#define B_SZ  64
#define HID   512
#define G3    1536
#define EMB_D 256
#define M_ROWS (S_LEN * B_SZ)   // 32768

typedef unsigned long long ull;

// ---------------- packed f32x2 helpers --------------------------------------
__device__ __forceinline__ ull pk2(float lo, float hi) {
    ull r; asm("mov.b64 %0, {%1,%2};" : "=l"(r) : "f"(lo), "f"(hi)); return r;
}
__device__ __forceinline__ ull dup2(float v) { return pk2(v, v); }
__device__ __forceinline__ void ffma2(ull& d, ull a, ull b) {
    asm("fma.rn.f32x2 %0, %1, %2, %0;" : "+l"(d) : "l"(a), "l"(b));
}
__device__ __forceinline__ float2 unpk2(ull v) {
    float2 f; asm("mov.b64 {%0,%1}, %2;" : "=f"(f.x), "=f"(f.y) : "l"(v)); return f;
}

// ---------------- scratch (static device globals; no allocation) ------------
__device__ float g_xemb[(size_t)M_ROWS * EMB_D];   // 32 MB
__device__ float g_xg  [(size_t)M_ROWS * G3];      // 192 MB
__device__ float g_ys  [(size_t)M_ROWS * HID];     // 64 MB
// one flag per producer block, each on its own 128B L2 line
__device__ unsigned int g_flags[4][32][32];

// ---------------- embedding gather ------------------------------------------
__global__ void embed_kernel(const int* __restrict__ x,
                             const float* __restrict__ emb,
                             float* __restrict__ out) {
    int w    = (blockIdx.x << 3) + (threadIdx.x >> 5);  // row m = s*64+b
    int lane = threadIdx.x & 31;
    int s = w >> 6, b = w & 63;
    int tok = x[b * S_LEN + s];
    float4* dst = (float4*)(out + (size_t)w * EMB_D);
    if (tok == 0) {  // PAD_IDX row zeroed
        float4 z = make_float4(0.f, 0.f, 0.f, 0.f);
        dst[lane] = z; dst[lane + 32] = z;
    } else {
        const float4* src = (const float4*)(emb + (size_t)tok * EMB_D);
        dst[lane] = src[lane]; dst[lane + 32] = src[lane + 32];
    }
}

// ---------------- C[M,N] = A[M,K] @ W[N,K]^T + bias[N] ----------------------
__global__ void __launch_bounds__(256, 2) gemm_bias_kernel(
    const float* __restrict__ A, const float* __restrict__ W,
    const float* __restrict__ bias, float* __restrict__ C,
    int M, int N, int K) {
    __shared__ float As[2][16][128];
    __shared__ float Bs[2][16][128];

    const int tid = threadIdx.x;
    const int n0 = blockIdx.x * 128;
    const int m0 = blockIdx.y * 128;
    const int tx = tid & 15, ty = tid >> 4;

    ull acc2[4][8];
#pragma unroll
    for (int p = 0; p < 4; p++)
#pragma unroll
        for (int j = 0; j < 8; j++) acc2[p][j] = 0ULL;

    const int KT = K >> 4;

#pragma unroll
    for (int i = 0; i < 2; i++) {
        int id = tid * 2 + i, row = id >> 2, kq = id & 3;
        float4 va = *(const float4*)(A + (size_t)(m0 + row) * K + kq * 4);
        float4 vb = *(const float4*)(W + (size_t)(n0 + row) * K + kq * 4);
        As[0][kq * 4 + 0][row] = va.x; As[0][kq * 4 + 1][row] = va.y;
        As[0][kq * 4 + 2][row] = va.z; As[0][kq * 4 + 3][row] = va.w;
        Bs[0][kq * 4 + 0][row] = vb.x; Bs[0][kq * 4 + 1][row] = vb.y;
        Bs[0][kq * 4 + 2][row] = vb.z; Bs[0][kq * 4 + 3][row] = vb.w;
    }
    __syncthreads();

    for (int kt = 0; kt < KT; ++kt) {
        const int cur = kt & 1;
        float4 pa[2], pb[2];
        const bool pf = (kt + 1) < KT;
        if (pf) {
#pragma unroll
            for (int i = 0; i < 2; i++) {
                int id = tid * 2 + i, row = id >> 2, kq = id & 3;
                pa[i] = *(const float4*)(A + (size_t)(m0 + row) * K + (kt + 1) * 16 + kq * 4);
                pb[i] = *(const float4*)(W + (size_t)(n0 + row) * K + (kt + 1) * 16 + kq * 4);
            }
        }
#pragma unroll
        for (int kk = 0; kk < 16; kk++) {
            ull ap[4];
            ap[0] = *(const ull*)&As[cur][kk][ty * 4];
            ap[1] = *(const ull*)&As[cur][kk][ty * 4 + 2];
            ap[2] = *(const ull*)&As[cur][kk][64 + ty * 4];
            ap[3] = *(const ull*)&As[cur][kk][64 + ty * 4 + 2];
            float b[8];
            *(float4*)(b)     = *(const float4*)&Bs[cur][kk][tx * 4];
            *(float4*)(b + 4) = *(const float4*)&Bs[cur][kk][64 + tx * 4];
#pragma unroll
            for (int j = 0; j < 8; j++) {
                ull bd = dup2(b[j]);
#pragma unroll
                for (int p = 0; p < 4; p++) ffma2(acc2[p][j], ap[p], bd);
            }
        }
        if (pf) {
            const int nxt = cur ^ 1;
#pragma unroll
            for (int i = 0; i < 2; i++) {
                int id = tid * 2 + i, row = id >> 2, kq = id & 3;
                As[nxt][kq * 4 + 0][row] = pa[i].x; As[nxt][kq * 4 + 1][row] = pa[i].y;
                As[nxt][kq * 4 + 2][row] = pa[i].z; As[nxt][kq * 4 + 3][row] = pa[i].w;
                Bs[nxt][kq * 4 + 0][row] = pb[i].x; Bs[nxt][kq * 4 + 1][row] = pb[i].y;
                Bs[nxt][kq * 4 + 2][row] = pb[i].z; Bs[nxt][kq * 4 + 3][row] = pb[i].w;
            }
        }
        __syncthreads();
    }

    float4 bb0 = *(const float4*)&bias[n0 + tx * 4];
    float4 bb1 = *(const float4*)&bias[n0 + 64 + tx * 4];
#pragma unroll
    for (int p = 0; p < 4; p++) {
        float2 c[8];
#pragma unroll
        for (int j = 0; j < 8; j++) c[j] = unpk2(acc2[p][j]);
#pragma unroll
        for (int half = 0; half < 2; half++) {
            int i = 2 * p + half;
            int m = m0 + ((i < 4) ? (ty * 4 + i) : (64 + ty * 4 + i - 4));
            float e[8];
#pragma unroll
            for (int j = 0; j < 8; j++) e[j] = half ? c[j].y : c[j].x;
            float4 v0 = make_float4(e[0] + bb0.x, e[1] + bb0.y,
                                    e[2] + bb0.z, e[3] + bb0.w);
            float4 v1 = make_float4(e[4] + bb1.x, e[5] + bb1.y,
                                    e[6] + bb1.z, e[7] + bb1.w);
            *(float4*)(C + (size_t)m * N + n0 + tx * 4)      = v0;
            *(float4*)(C + (size_t)m * N + n0 + 64 + tx * 4) = v1;
        }
    }
}

// ---------------- GRU recurrence ---------------------------------------------
// 128 blocks = 4 batch groups (16 rows) x 32 dim groups (16 dims), 512 threads.
// Warp w computes k range [32w, 32w+32) == h-chunks of producer blocks 2w, 2w+1.
// Staging (poll + LDG + STS) is warp-private: no __syncthreads in the load path.
// smem: Wsh [512][48] k-major (col = dimLocal*3+gate)  = 96KB
//       hsh [512][16] swizzled by ((k>>1)^(k>>5))&15   = 32KB
//       part[16 kgroups][256 rowdim][4]                = 64KB
#define GRU_SMEM_BYTES ((512 * 48 + 512 * 16 + 16 * 256 * 4) * 4)

__device__ __forceinline__ unsigned ld_acq(const unsigned* p) {
    unsigned v;
    asm volatile("ld.global.acquire.gpu.u32 %0, [%1];" : "=r"(v) : "l"(p) : "memory");
    return v;
}
__device__ __forceinline__ void st_rel(unsigned* p, unsigned v) {
    asm volatile("st.global.release.gpu.u32 [%0], %1;" :: "l"(p), "r"(v) : "memory");
}
__device__ __forceinline__ int hswz(int k) { return ((k >> 1) ^ (k >> 5)) & 15; }

__global__ void __launch_bounds__(512, 1) gru_kernel(
    const float* __restrict__ xg,    // [S][64][1536]
    const float* __restrict__ Whh,   // [1536][512]
    const float* __restrict__ bhh,   // [1536]
    float* __restrict__ ys)          // [S][64][512]
{
    extern __shared__ float sm[];
    float* Wsh  = sm;                  // 512*48
    float* hsh  = Wsh + 512 * 48;      // 512*16
    float* part = hsh + 512 * 16;      // 16*256*4
    __shared__ unsigned sh_base;

    const int tid = threadIdx.x;
    const int bg  = blockIdx.x & 3;
    const int dg  = blockIdx.x >> 2;
    const int rowBase = bg * 16;
    const int dimBase = dg * 16;

    if (tid == 0) sh_base = *(volatile unsigned*)&g_flags[bg][dg][0];

    // load W_hh slice (48 gate rows) into smem, k-major
    for (int idx = tid; idx < 48 * 512; idx += 512) {
        int col = idx >> 9;       // 0..47
        int k   = idx & 511;
        int dl = col / 3, g = col % 3;
        int grow = g * 512 + dimBase + dl;
        Wsh[k * 48 + col] = Whh[(size_t)grow * 512 + k];
    }

    // gating role (tid < 256): one thread per (row, dim)
    const int myrow = (tid >> 4) & 15;
    const int mydl  = tid & 15;
    const int mydim = dimBase + mydl;
    float b_r = 0.f, b_z = 0.f, b_n = 0.f;
    if (tid < 256) {
        b_r = bhh[mydim]; b_z = bhh[512 + mydim]; b_n = bhh[1024 + mydim];
    }

    // compute role: warp w owns k in [32w, 32w+32); lane tile r4 x d2 x g3
    const int w    = tid >> 5;
    const int lane = tid & 31;
    const int rg   = lane >> 3;           // rows 4rg..4rg+3
    const int dgi  = lane & 7;            // dims {2dgi, 2dgi+1}
    const int k0   = w * 32;

    __syncthreads();
    const unsigned base = sh_base;

    for (int t = 0; t < S_LEN; ++t) {
        // xg prefetch for gating (issued early, consumed at gate time)
        float xr = 0.f, xz = 0.f, xn = 0.f;
        if (tid < 256) {
            size_t xbase = ((size_t)t * 64 + rowBase + myrow) * G3 + mydim;
            xr = xg[xbase]; xz = xg[xbase + 512]; xn = xg[xbase + 1024];
        }

        // ---- warp-private h staging: poll 2 producer flags, LDG, STS ----
        if (t == 0) {
            for (int idx = lane; idx < 32 * 16; idx += 32) hsh[k0 * 16 + idx] = 0.f;
            __syncwarp();
        } else {
            const unsigned target = base + (unsigned)t;
            const float4* hsrc4 = (const float4*)(ys + ((size_t)(t - 1) * 64 + rowBase) * HID);
            float4 v[2][2];
#pragma unroll
            for (int j = 0; j < 2; j++) {
                const int c = 2 * w + j;
                const unsigned* fp = &g_flags[bg][c][0];
                while ((int)(ld_acq(fp) - target) < 0) { }
#pragma unroll
                for (int i = 0; i < 2; i++) {
                    int idx = i * 32 + lane;
                    int r = idx & 15, fq = idx >> 4;
                    v[j][i] = __ldcg(hsrc4 + (size_t)r * 128 + c * 4 + fq);
                }
            }
#pragma unroll
            for (int j = 0; j < 2; j++) {
                const int c = 2 * w + j;
#pragma unroll
                for (int i = 0; i < 2; i++) {
                    int idx = i * 32 + lane;
                    int r = idx & 15, fq = idx >> 4;
                    int kb = c * 16 + fq * 4;
                    hsh[(kb + 0) * 16 + (r ^ hswz(kb + 0))] = v[j][i].x;
                    hsh[(kb + 1) * 16 + (r ^ hswz(kb + 1))] = v[j][i].y;
                    hsh[(kb + 2) * 16 + (r ^ hswz(kb + 2))] = v[j][i].z;
                    hsh[(kb + 3) * 16 + (r ^ hswz(kb + 3))] = v[j][i].w;
                }
            }
            __syncwarp();
        }

        // ---- GEMM over this warp's 32 k: acc = 4 rows x 2 dims x 3 gates ----
        ull acc2[12];
#pragma unroll
        for (int i = 0; i < 12; i++) acc2[i] = 0ULL;
        const float* Wp = Wsh + dgi * 6;
        const int rb = rg * 4;
#pragma unroll 4
        for (int k = k0; k < k0 + 32; ++k) {
            const float* wk = Wp + k * 48;
            ull w01 = *(const ull*)(wk);
            ull w23 = *(const ull*)(wk + 2);
            ull w45 = *(const ull*)(wk + 4);
            const int sw = hswz(k);
            const float* hk = hsh + k * 16;
            ull h0 = dup2(hk[(rb + 0) ^ sw]);
            ull h1 = dup2(hk[(rb + 1) ^ sw]);
            ull h2 = dup2(hk[(rb + 2) ^ sw]);
            ull h3 = dup2(hk[(rb + 3) ^ sw]);
            ffma2(acc2[0],  h0, w01); ffma2(acc2[1],  h0, w23); ffma2(acc2[2],  h0, w45);
            ffma2(acc2[3],  h1, w01); ffma2(acc2[4],  h1, w23); ffma2(acc2[5],  h1, w45);
            ffma2(acc2[6],  h2, w01); ffma2(acc2[7],  h2, w23); ffma2(acc2[8],  h2, w45);
            ffma2(acc2[9],  h3, w01); ffma2(acc2[10], h3, w23); ffma2(acc2[11], h3, w45);
        }
        // partials: per row i: (d0: r,z,n) (d1: r,z,n)
#pragma unroll
        for (int i = 0; i < 4; i++) {
            float2 v0 = unpk2(acc2[i * 3 + 0]);   // d0r, d0z
            float2 v1 = unpk2(acc2[i * 3 + 1]);   // d0n, d1r
            float2 v2 = unpk2(acc2[i * 3 + 2]);   // d1z, d1n
            int rd = (rb + i) * 16 + dgi * 2;
            float* p = part + (w * 256 + rd) * 4;
            *(float4*)(p)     = make_float4(v0.x, v0.y, v1.x, 0.f);
            *(float4*)(p + 4) = make_float4(v1.y, v2.x, v2.y, 0.f);
        }
        __syncthreads();

        // ---- reduce 16 k-groups + gate, one thread per (row, dim) ----
        if (tid < 256) {
            float hr = b_r, hz = b_z, hn = b_n;
#pragma unroll
            for (int kk = 0; kk < 16; kk++) {
                float4 p = *(const float4*)(part + (kk * 256 + tid) * 4);
                hr += p.x; hz += p.y; hn += p.z;
            }
            float h_old = hsh[mydim * 16 + (myrow ^ hswz(mydim))];
            float er = __expf(-(xr + hr));
            float rr = __fdividef(1.f, 1.f + er);
            float ez = __expf(-(xz + hz));
            float zz = __fdividef(1.f, 1.f + ez);
            float an = xn + rr * hn;
            float e2 = __expf(2.f * an);
            float nn = 1.f - __fdividef(2.f, e2 + 1.f);   // tanh(an)
            float hnew = (1.f - zz) * nn + zz * h_old;
            ys[((size_t)t * 64 + rowBase + myrow) * HID + mydim] = hnew;
        }

        __syncthreads();   // h written + part consumed before flag release / reuse
        if (tid == 0) st_rel(&g_flags[bg][dg][0], base + (unsigned)t + 1u);
    }
}

// ---------------- final FC + sigmoid ----------------------------------------
__global__ void fc_kernel(const float* __restrict__ ys,
                          const float* __restrict__ Wfc,
                          const float* __restrict__ bfc,
                          float* __restrict__ out) {
    int b = blockIdx.x, tid = threadIdx.x;  // 128 threads
    const float* h = ys + ((size_t)(S_LEN - 1) * 64 + b) * HID;
    float s = 0.f;
    for (int i = tid; i < HID; i += 128) s += h[i] * Wfc[i];
#pragma unroll
    for (int o = 16; o; o >>= 1) s += __shfl_down_sync(0xffffffffu, s, o);
    __shared__ float ps[4];
    if ((tid & 31) == 0) ps[tid >> 5] = s;
    __syncthreads();
    if (tid == 0) {
        float v = ps[0] + ps[1] + ps[2] + ps[3] + bfc[0];
        out[b] = 1.f / (1.f + expf(-v));
    }
}

// ---------------- launch ----------------------------------------------------
extern "C" void kernel_launch(void* const* d_in, const int* in_sizes, int n_in,
                              void* d_out, int out_size) {
    (void)in_sizes; (void)n_in; (void)out_size;
    const int*   x    = (const int*)  d_in[0];
    const float* emb  = (const float*)d_in[1];
    const float* Wih0 = (const float*)d_in[2];
    const float* Whh0 = (const float*)d_in[3];
    const float* bih0 = (const float*)d_in[4];
    const float* bhh0 = (const float*)d_in[5];
    const float* Wih1 = (const float*)d_in[6];
    const float* Whh1 = (const float*)d_in[7];
    const float* bih1 = (const float*)d_in[8];
    const float* bhh1 = (const float*)d_in[9];
    const float* Wfc  = (const float*)d_in[10];
    const float* bfc  = (const float*)d_in[11];
    float* out = (float*)d_out;

    float *xemb, *xgbuf, *ysbuf;
    cudaGetSymbolAddress((void**)&xemb,  g_xemb);
    cudaGetSymbolAddress((void**)&xgbuf, g_xg);
    cudaGetSymbolAddress((void**)&ysbuf, g_ys);

    cudaFuncSetAttribute(gru_kernel, cudaFuncAttributeMaxDynamicSharedMemorySize,
                         GRU_SMEM_BYTES);

    embed_kernel<<<4096, 256>>>(x, emb, xemb);
    gemm_bias_kernel<<<dim3(G3 / 128, M_ROWS / 128), 256>>>(
        xemb, Wih0, bih0, xgbuf, M_ROWS, G3, EMB_D);
    gru_kernel<<<128, 512, GRU_SMEM_BYTES>>>(xgbuf, Whh0, bhh0, ysbuf);
    gemm_bias_kernel<<<dim3(G3 / 128, M_ROWS / 128), 256>>>(
        ysbuf, Wih1, bih1, xgbuf, M_ROWS, G3, HID);
    gru_kernel<<<128, 512, GRU_SMEM_BYTES>>>(xgbuf, Whh1, bhh1, ysbuf);
    fc_kernel<<<64, 128>>>(ysbuf, Wfc, bfc, out);
}

// round 8
// speedup vs baseline: 1.1238x; 1.0022x over previous
#include <cuda_runtime.h>
#include <math.h>

#define S_LEN 512
#define B_SZ  64
#define HID   512
#define G3    1536
#define EMB_D 256
#define M_ROWS (S_LEN * B_SZ)   // 32768

typedef unsigned long long ull;

// ---------------- packed f32x2 helpers --------------------------------------
__device__ __forceinline__ ull pk2(float lo, float hi) {
    ull r; asm("mov.b64 %0, {%1,%2};" : "=l"(r) : "f"(lo), "f"(hi)); return r;
}
__device__ __forceinline__ ull dup2(float v) { return pk2(v, v); }
__device__ __forceinline__ void ffma2(ull& d, ull a, ull b) {
    asm("fma.rn.f32x2 %0, %1, %2, %0;" : "+l"(d) : "l"(a), "l"(b));
}
__device__ __forceinline__ ull add2(ull a, ull b) {
    ull r; asm("add.rn.f32x2 %0, %1, %2;" : "=l"(r) : "l"(a), "l"(b)); return r;
}
__device__ __forceinline__ float2 unpk2(ull v) {
    float2 f; asm("mov.b64 {%0,%1}, %2;" : "=f"(f.x), "=f"(f.y) : "l"(v)); return f;
}

// ---------------- scratch (static device globals; no allocation) ------------
__device__ float g_xemb[(size_t)M_ROWS * EMB_D];   // 32 MB
__device__ float g_xg  [(size_t)M_ROWS * G3];      // 192 MB
__device__ float g_ys  [(size_t)M_ROWS * HID];     // 64 MB
__device__ unsigned int g_flags[4][32][32];         // one flag per 128B line

// ---------------- embedding gather ------------------------------------------
__global__ void embed_kernel(const int* __restrict__ x,
                             const float* __restrict__ emb,
                             float* __restrict__ out) {
    int w    = (blockIdx.x << 3) + (threadIdx.x >> 5);
    int lane = threadIdx.x & 31;
    int s = w >> 6, b = w & 63;
    int tok = x[b * S_LEN + s];
    float4* dst = (float4*)(out + (size_t)w * EMB_D);
    if (tok == 0) {
        float4 z = make_float4(0.f, 0.f, 0.f, 0.f);
        dst[lane] = z; dst[lane + 32] = z;
    } else {
        const float4* src = (const float4*)(emb + (size_t)tok * EMB_D);
        dst[lane] = src[lane]; dst[lane + 32] = src[lane + 32];
    }
}

// ---------------- C[M,N] = A[M,K] @ W[N,K]^T + bias[N] ----------------------
__global__ void __launch_bounds__(256, 2) gemm_bias_kernel(
    const float* __restrict__ A, const float* __restrict__ W,
    const float* __restrict__ bias, float* __restrict__ C,
    int M, int N, int K) {
    __shared__ float As[2][16][128];
    __shared__ float Bs[2][16][128];

    const int tid = threadIdx.x;
    const int n0 = blockIdx.x * 128;
    const int m0 = blockIdx.y * 128;
    const int tx = tid & 15, ty = tid >> 4;

    ull acc2[4][8];
#pragma unroll
    for (int p = 0; p < 4; p++)
#pragma unroll
        for (int j = 0; j < 8; j++) acc2[p][j] = 0ULL;

    const int KT = K >> 4;

#pragma unroll
    for (int i = 0; i < 2; i++) {
        int id = tid * 2 + i, row = id >> 2, kq = id & 3;
        float4 va = *(const float4*)(A + (size_t)(m0 + row) * K + kq * 4);
        float4 vb = *(const float4*)(W + (size_t)(n0 + row) * K + kq * 4);
        As[0][kq * 4 + 0][row] = va.x; As[0][kq * 4 + 1][row] = va.y;
        As[0][kq * 4 + 2][row] = va.z; As[0][kq * 4 + 3][row] = va.w;
        Bs[0][kq * 4 + 0][row] = vb.x; Bs[0][kq * 4 + 1][row] = vb.y;
        Bs[0][kq * 4 + 2][row] = vb.z; Bs[0][kq * 4 + 3][row] = vb.w;
    }
    __syncthreads();

    for (int kt = 0; kt < KT; ++kt) {
        const int cur = kt & 1;
        float4 pa[2], pb[2];
        const bool pf = (kt + 1) < KT;
        if (pf) {
#pragma unroll
            for (int i = 0; i < 2; i++) {
                int id = tid * 2 + i, row = id >> 2, kq = id & 3;
                pa[i] = *(const float4*)(A + (size_t)(m0 + row) * K + (kt + 1) * 16 + kq * 4);
                pb[i] = *(const float4*)(W + (size_t)(n0 + row) * K + (kt + 1) * 16 + kq * 4);
            }
        }
#pragma unroll
        for (int kk = 0; kk < 16; kk++) {
            ulonglong2 a01 = *(const ulonglong2*)&As[cur][kk][ty * 4];
            ulonglong2 a23 = *(const ulonglong2*)&As[cur][kk][64 + ty * 4];
            ull ap[4] = { a01.x, a01.y, a23.x, a23.y };
            float b[8];
            *(float4*)(b)     = *(const float4*)&Bs[cur][kk][tx * 4];
            *(float4*)(b + 4) = *(const float4*)&Bs[cur][kk][64 + tx * 4];
#pragma unroll
            for (int j = 0; j < 8; j++) {
                ull bd = dup2(b[j]);
#pragma unroll
                for (int p = 0; p < 4; p++) ffma2(acc2[p][j], ap[p], bd);
            }
        }
        if (pf) {
            const int nxt = cur ^ 1;
#pragma unroll
            for (int i = 0; i < 2; i++) {
                int id = tid * 2 + i, row = id >> 2, kq = id & 3;
                As[nxt][kq * 4 + 0][row] = pa[i].x; As[nxt][kq * 4 + 1][row] = pa[i].y;
                As[nxt][kq * 4 + 2][row] = pa[i].z; As[nxt][kq * 4 + 3][row] = pa[i].w;
                Bs[nxt][kq * 4 + 0][row] = pb[i].x; Bs[nxt][kq * 4 + 1][row] = pb[i].y;
                Bs[nxt][kq * 4 + 2][row] = pb[i].z; Bs[nxt][kq * 4 + 3][row] = pb[i].w;
            }
        }
        __syncthreads();
    }

    float4 bb0 = *(const float4*)&bias[n0 + tx * 4];
    float4 bb1 = *(const float4*)&bias[n0 + 64 + tx * 4];
#pragma unroll
    for (int p = 0; p < 4; p++) {
        float2 c[8];
#pragma unroll
        for (int j = 0; j < 8; j++) c[j] = unpk2(acc2[p][j]);
#pragma unroll
        for (int half = 0; half < 2; half++) {
            int i = 2 * p + half;
            int m = m0 + ((i < 4) ? (ty * 4 + i) : (64 + ty * 4 + i - 4));
            float e[8];
#pragma unroll
            for (int j = 0; j < 8; j++) e[j] = half ? c[j].y : c[j].x;
            float4 v0 = make_float4(e[0] + bb0.x, e[1] + bb0.y,
                                    e[2] + bb0.z, e[3] + bb0.w);
            float4 v1 = make_float4(e[4] + bb1.x, e[5] + bb1.y,
                                    e[6] + bb1.z, e[7] + bb1.w);
            *(float4*)(C + (size_t)m * N + n0 + tx * 4)      = v0;
            *(float4*)(C + (size_t)m * N + n0 + 64 + tx * 4) = v1;
        }
    }
}

// ---------------- GRU recurrence ---------------------------------------------
// 128 blocks = 4 batch groups (16 rows) x 32 dim groups (16 dims), 512 threads.
// Warp w stages+computes k in [32w, 32w+32): half-lanes 0-15 do k, 16-31 do k+16.
// Lane tile: 4 rows x 4 dims x 3 gates (24 f32x2 acc). Halves merge via shfl(16).
// WSH_STRIDE must be EVEN (w operands are LDS.64); half-warp W collisions land
// in different LDS.64 phases, so no padding needed.
#define WSH_STRIDE 48
#define HSH_STRIDE 17
#define PART_RSTRIDE 20
#define GRU_SMEM_FLOATS (512 * WSH_STRIDE + 512 * HSH_STRIDE + 16 * 3 * 16 * PART_RSTRIDE)
#define GRU_SMEM_BYTES  (GRU_SMEM_FLOATS * 4)

__device__ __forceinline__ unsigned ld_acq(const unsigned* p) {
    unsigned v;
    asm volatile("ld.global.acquire.gpu.u32 %0, [%1];" : "=r"(v) : "l"(p) : "memory");
    return v;
}
__device__ __forceinline__ void st_rel(unsigned* p, unsigned v) {
    asm volatile("st.global.release.gpu.u32 [%0], %1;" :: "l"(p), "r"(v) : "memory");
}
__device__ __forceinline__ int hswz(int k) { return ((k >> 1) ^ (k >> 5)) & 15; }

__global__ void __launch_bounds__(512, 1) gru_kernel(
    const float* __restrict__ xg,    // [S][64][1536]
    const float* __restrict__ Whh,   // [1536][512]
    const float* __restrict__ bhh,   // [1536]
    float* __restrict__ ys)          // [S][64][512]
{
    extern __shared__ float sm[];
    float* Wsh  = sm;
    float* hsh  = Wsh + 512 * WSH_STRIDE;
    float* part = hsh + 512 * HSH_STRIDE;
    __shared__ unsigned sh_base;

    const int tid = threadIdx.x;
    const int bg  = blockIdx.x & 3;
    const int dg  = blockIdx.x >> 2;
    const int rowBase = bg * 16;
    const int dimBase = dg * 16;

    if (tid == 0) sh_base = *(volatile unsigned*)&g_flags[bg][dg][0];

    // load W_hh slice (48 gate cols) into smem, k-major
    for (int idx = tid; idx < 48 * 512; idx += 512) {
        int col = idx >> 9;       // 0..47  (col = dimLocal*3 + gate)
        int k   = idx & 511;
        int dl = col / 3, g = col % 3;
        int grow = g * 512 + dimBase + dl;
        Wsh[k * WSH_STRIDE + col] = Whh[(size_t)grow * 512 + k];
    }

    // gating role (tid < 256): one thread per (row, dim)
    const int myrow = (tid >> 4) & 15;
    const int mydl  = tid & 15;
    const int mydim = dimBase + mydl;
    float b_r = 0.f, b_z = 0.f, b_n = 0.f;
    if (tid < 256) {
        b_r = bhh[mydim]; b_z = bhh[512 + mydim]; b_n = bhh[1024 + mydim];
    }

    // compute role
    const int w    = tid >> 5;            // warp 0..15, k chunk [32w, 32w+32)
    const int lane = tid & 31;
    const int half = lane >> 4;           // 0: k, 1: k+16
    const int l    = lane & 15;
    const int rg   = l >> 2;              // row group: rows 4rg..4rg+3
    const int dgi  = l & 3;               // dim group: local dims 4dgi..4dgi+3
    const int rb   = rg * 4;
    const int k0   = w * 32;

    __syncthreads();
    const unsigned base = sh_base;

    for (int t = 0; t < S_LEN; ++t) {
        // xg prefetch for gating
        float xr = 0.f, xz = 0.f, xn = 0.f;
        if (tid < 256) {
            size_t xbase = ((size_t)t * 64 + rowBase + myrow) * G3 + mydim;
            xr = xg[xbase]; xz = xg[xbase + 512]; xn = xg[xbase + 1024];
        }

        // ---- warp-private h staging ----
        if (t == 0) {
            for (int idx = lane; idx < 32 * HSH_STRIDE; idx += 32)
                hsh[k0 * HSH_STRIDE + idx] = 0.f;
            __syncwarp();
        } else {
            const unsigned target = base + (unsigned)t;
            const float4* hsrc4 = (const float4*)(ys + ((size_t)(t - 1) * 64 + rowBase) * HID);
            float4 v[2][2];
#pragma unroll
            for (int j = 0; j < 2; j++) {
                const int c = 2 * w + j;   // producer chunk (16 dims = 16 k)
                const unsigned* fp = &g_flags[bg][c][0];
                while ((int)(ld_acq(fp) - target) < 0) { }
#pragma unroll
                for (int i = 0; i < 2; i++) {
                    int idx = i * 32 + lane;
                    int r = idx & 15, fq = idx >> 4;
                    v[j][i] = __ldcg(hsrc4 + (size_t)r * 128 + c * 4 + fq);
                }
            }
#pragma unroll
            for (int j = 0; j < 2; j++) {
                const int c = 2 * w + j;
#pragma unroll
                for (int i = 0; i < 2; i++) {
                    int idx = i * 32 + lane;
                    int r = idx & 15, fq = idx >> 4;
                    int kb = c * 16 + fq * 4;
                    hsh[(kb + 0) * HSH_STRIDE + (r ^ hswz(kb + 0))] = v[j][i].x;
                    hsh[(kb + 1) * HSH_STRIDE + (r ^ hswz(kb + 1))] = v[j][i].y;
                    hsh[(kb + 2) * HSH_STRIDE + (r ^ hswz(kb + 2))] = v[j][i].z;
                    hsh[(kb + 3) * HSH_STRIDE + (r ^ hswz(kb + 3))] = v[j][i].w;
                }
            }
            __syncwarp();
        }

        // ---- GEMM: 16 iterations, half-lane handles one k per iteration ----
        ull acc2[24];   // [4 rows][6 col-pairs]
#pragma unroll
        for (int i = 0; i < 24; i++) acc2[i] = 0ULL;
#pragma unroll 2
        for (int it = 0; it < 16; ++it) {
            const int k = k0 + it + half * 16;
            const float* wk = Wsh + k * WSH_STRIDE + dgi * 12;
            ull w0 = *(const ull*)(wk);
            ull w1 = *(const ull*)(wk + 2);
            ull w2 = *(const ull*)(wk + 4);
            ull w3 = *(const ull*)(wk + 6);
            ull w4 = *(const ull*)(wk + 8);
            ull w5 = *(const ull*)(wk + 10);
            const int sw = hswz(k);
            const float* hk = hsh + k * HSH_STRIDE;
            ull h0 = dup2(hk[(rb + 0) ^ sw]);
            ull h1 = dup2(hk[(rb + 1) ^ sw]);
            ull h2 = dup2(hk[(rb + 2) ^ sw]);
            ull h3 = dup2(hk[(rb + 3) ^ sw]);
            ffma2(acc2[0],  h0, w0); ffma2(acc2[1],  h0, w1); ffma2(acc2[2],  h0, w2);
            ffma2(acc2[3],  h0, w3); ffma2(acc2[4],  h0, w4); ffma2(acc2[5],  h0, w5);
            ffma2(acc2[6],  h1, w0); ffma2(acc2[7],  h1, w1); ffma2(acc2[8],  h1, w2);
            ffma2(acc2[9],  h1, w3); ffma2(acc2[10], h1, w4); ffma2(acc2[11], h1, w5);
            ffma2(acc2[12], h2, w0); ffma2(acc2[13], h2, w1); ffma2(acc2[14], h2, w2);
            ffma2(acc2[15], h2, w3); ffma2(acc2[16], h2, w4); ffma2(acc2[17], h2, w5);
            ffma2(acc2[18], h3, w0); ffma2(acc2[19], h3, w1); ffma2(acc2[20], h3, w2);
            ffma2(acc2[21], h3, w3); ffma2(acc2[22], h3, w4); ffma2(acc2[23], h3, w5);
        }

        // ---- merge halves: lane l += lane l+16 ----
#pragma unroll
        for (int i = 0; i < 24; i++) {
            ull o = __shfl_down_sync(0xffffffffu, acc2[i], 16);
            acc2[i] = add2(acc2[i], o);   // only lanes<16 hold valid sums
        }

        // ---- write partials (lanes < 16): gate-major float4 per row ----
        if (half == 0) {
#pragma unroll
            for (int j = 0; j < 4; j++) {
                float2 p0 = unpk2(acc2[j * 6 + 0]);
                float2 p1 = unpk2(acc2[j * 6 + 1]);
                float2 p2 = unpk2(acc2[j * 6 + 2]);
                float2 p3 = unpk2(acc2[j * 6 + 3]);
                float2 p4 = unpk2(acc2[j * 6 + 4]);
                float2 p5 = unpk2(acc2[j * 6 + 5]);
                int row = rb + j;
                float* pp = part + ((w * 3 + 0) * 16 + row) * PART_RSTRIDE + dgi * 4;
                *(float4*)pp = make_float4(p0.x, p1.y, p3.x, p4.y);   // gate r
                pp = part + ((w * 3 + 1) * 16 + row) * PART_RSTRIDE + dgi * 4;
                *(float4*)pp = make_float4(p0.y, p2.x, p3.y, p5.x);   // gate z
                pp = part + ((w * 3 + 2) * 16 + row) * PART_RSTRIDE + dgi * 4;
                *(float4*)pp = make_float4(p1.x, p2.y, p4.x, p5.y);   // gate n
            }
        }
        __syncthreads();

        // ---- reduce 16 k-groups + gate, one thread per (row, dim) ----
        if (tid < 256) {
            float hr = b_r, hz = b_z, hn = b_n;
#pragma unroll
            for (int kk = 0; kk < 16; kk++) {
                hr += part[((kk * 3 + 0) * 16 + myrow) * PART_RSTRIDE + mydl];
                hz += part[((kk * 3 + 1) * 16 + myrow) * PART_RSTRIDE + mydl];
                hn += part[((kk * 3 + 2) * 16 + myrow) * PART_RSTRIDE + mydl];
            }
            float h_old = hsh[mydim * HSH_STRIDE + (myrow ^ hswz(mydim))];
            float er = __expf(-(xr + hr));
            float rr = __fdividef(1.f, 1.f + er);
            float ez = __expf(-(xz + hz));
            float zz = __fdividef(1.f, 1.f + ez);
            float an = xn + rr * hn;
            float e2 = __expf(2.f * an);
            float nn = 1.f - __fdividef(2.f, e2 + 1.f);   // tanh(an)
            float hnew = (1.f - zz) * nn + zz * h_old;
            ys[((size_t)t * 64 + rowBase + myrow) * HID + mydim] = hnew;
        }

        __syncthreads();
        if (tid == 0) st_rel(&g_flags[bg][dg][0], base + (unsigned)t + 1u);
    }
}

// ---------------- final FC + sigmoid ----------------------------------------
__global__ void fc_kernel(const float* __restrict__ ys,
                          const float* __restrict__ Wfc,
                          const float* __restrict__ bfc,
                          float* __restrict__ out) {
    int b = blockIdx.x, tid = threadIdx.x;
    const float* h = ys + ((size_t)(S_LEN - 1) * 64 + b) * HID;
    float s = 0.f;
    for (int i = tid; i < HID; i += 128) s += h[i] * Wfc[i];
#pragma unroll
    for (int o = 16; o; o >>= 1) s += __shfl_down_sync(0xffffffffu, s, o);
    __shared__ float ps[4];
    if ((tid & 31) == 0) ps[tid >> 5] = s;
    __syncthreads();
    if (tid == 0) {
        float v = ps[0] + ps[1] + ps[2] + ps[3] + bfc[0];
        out[b] = 1.f / (1.f + expf(-v));
    }
}

// ---------------- launch ----------------------------------------------------
extern "C" void kernel_launch(void* const* d_in, const int* in_sizes, int n_in,
                              void* d_out, int out_size) {
    (void)in_sizes; (void)n_in; (void)out_size;
    const int*   x    = (const int*)  d_in[0];
    const float* emb  = (const float*)d_in[1];
    const float* Wih0 = (const float*)d_in[2];
    const float* Whh0 = (const float*)d_in[3];
    const float* bih0 = (const float*)d_in[4];
    const float* bhh0 = (const float*)d_in[5];
    const float* Wih1 = (const float*)d_in[6];
    const float* Whh1 = (const float*)d_in[7];
    const float* bih1 = (const float*)d_in[8];
    const float* bhh1 = (const float*)d_in[9];
    const float* Wfc  = (const float*)d_in[10];
    const float* bfc  = (const float*)d_in[11];
    float* out = (float*)d_out;

    float *xemb, *xgbuf, *ysbuf;
    cudaGetSymbolAddress((void**)&xemb,  g_xemb);
    cudaGetSymbolAddress((void**)&xgbuf, g_xg);
    cudaGetSymbolAddress((void**)&ysbuf, g_ys);

    cudaFuncSetAttribute(gru_kernel, cudaFuncAttributeMaxDynamicSharedMemorySize,
                         GRU_SMEM_BYTES);

    embed_kernel<<<4096, 256>>>(x, emb, xemb);
    gemm_bias_kernel<<<dim3(G3 / 128, M_ROWS / 128), 256>>>(
        xemb, Wih0, bih0, xgbuf, M_ROWS, G3, EMB_D);
    gru_kernel<<<128, 512, GRU_SMEM_BYTES>>>(xgbuf, Whh0, bhh0, ysbuf);
    gemm_bias_kernel<<<dim3(G3 / 128, M_ROWS / 128), 256>>>(
        ysbuf, Wih1, bih1, xgbuf, M_ROWS, G3, HID);
    gru_kernel<<<128, 512, GRU_SMEM_BYTES>>>(xgbuf, Whh1, bhh1, ysbuf);
    fc_kernel<<<64, 128>>>(ysbuf, Wfc, bfc, out);
}